// round 3
// baseline (speedup 1.0000x reference)
#include <cuda_runtime.h>
#include <math.h>

#define TT 256
#define BB 256
#define DD 512
#define HH 512
#define NG 2048  // 4*H

// ---------------- scratch (static device globals; no allocations) ----------
__device__ float g_mask[4];
__device__ float g_bc[NG];                       // b3 @ Wg_top + gate_b
__device__ float g_W3g[64 * NG];                 // W3 @ Wg_top
__device__ float g_h1[(size_t)TT * BB * 128];
__device__ float g_h2[(size_t)TT * BB * 64];
__device__ float g_Z[(size_t)TT * BB * NG];      // precomputed input-gate contributions
__device__ float g_zero[BB * HH];                // never written -> stays zero

// ---------------- tiny kernels --------------------------------------------
__global__ void mask_kernel(const float* __restrict__ w1, const float* __restrict__ b1,
                            const float* __restrict__ w2, const float* __restrict__ b2) {
    if (threadIdx.x == 0) {
        float t[8];
        for (int j = 0; j < 8; j++) {
            float s = b1[j];
            for (int i = 0; i < 4; i++) s += w1[i * 8 + j];
            t[j] = tanhf(s);
        }
        float z[4];
        float mx = -1e30f;
        for (int k = 0; k < 4; k++) {
            float s = b2[k];
            for (int j = 0; j < 8; j++) s += t[j] * w2[j * 4 + k];
            z[k] = s;
            mx = fmaxf(mx, s);
        }
        float den = 0.f;
        for (int k = 0; k < 4; k++) { z[k] = expf(z[k] - mx); den += z[k]; }
        for (int k = 0; k < 4; k++) g_mask[k] = z[k] / den;
    }
}

__global__ void bias_kernel(const float* __restrict__ gate_w, const float* __restrict__ gate_b,
                            const float* __restrict__ b3) {
    int n = blockIdx.x * blockDim.x + threadIdx.x;
    if (n < NG) {
        float s = gate_b[n];
        for (int k = 0; k < DD; k++) s += b3[k] * gate_w[(size_t)k * NG + n];
        g_bc[n] = s;
    }
}

__global__ void zero_kernel(float* __restrict__ p, int n) {
    int i = blockIdx.x * blockDim.x + threadIdx.x;
    if (i < n) p[i] = 0.f;
}

// ---------------- generic fp32 GEMM: C = act(A@B + bias) -------------------
// A [M,K] row-major, B [K,N] row-major. M%64==0 (or M==64), N%64==0, K%16==0.
template <int ACT>
__global__ __launch_bounds__(256) void sgemm(const float* __restrict__ A,
                                             const float* __restrict__ B,
                                             const float* __restrict__ bias,
                                             float* __restrict__ C,
                                             int M, int N, int K) {
    __shared__ float As[16][68];
    __shared__ float Bs[16][64];
    const int tid = threadIdx.x;
    const int m0 = blockIdx.y << 6, n0 = blockIdx.x << 6;
    const int tx = tid & 15, ty = tid >> 4;
    const int ar = tid >> 2, ak = (tid & 3) << 2;
    const int bk = tid >> 4, bn = (tid & 15) << 2;

    float acc[4][4];
#pragma unroll
    for (int i = 0; i < 4; i++)
#pragma unroll
        for (int j = 0; j < 4; j++) acc[i][j] = 0.f;

    const float* Aptr = A + (size_t)(m0 + ar) * K + ak;
    const float* Bptr = B + (size_t)bk * N + n0 + bn;

    for (int k0 = 0; k0 < K; k0 += 16) {
        float4 av = *(const float4*)(Aptr + k0);
        float4 bv = *(const float4*)(Bptr + (size_t)k0 * N);
        As[ak + 0][ar] = av.x; As[ak + 1][ar] = av.y;
        As[ak + 2][ar] = av.z; As[ak + 3][ar] = av.w;
        *(float4*)&Bs[bk][bn] = bv;
        __syncthreads();
#pragma unroll
        for (int k = 0; k < 16; k++) {
            float4 b4 = *(const float4*)&Bs[k][tx << 2];
            float a0 = As[k][(ty << 2) + 0], a1 = As[k][(ty << 2) + 1];
            float a2 = As[k][(ty << 2) + 2], a3 = As[k][(ty << 2) + 3];
            acc[0][0] += a0 * b4.x; acc[0][1] += a0 * b4.y; acc[0][2] += a0 * b4.z; acc[0][3] += a0 * b4.w;
            acc[1][0] += a1 * b4.x; acc[1][1] += a1 * b4.y; acc[1][2] += a1 * b4.z; acc[1][3] += a1 * b4.w;
            acc[2][0] += a2 * b4.x; acc[2][1] += a2 * b4.y; acc[2][2] += a2 * b4.z; acc[2][3] += a2 * b4.w;
            acc[3][0] += a3 * b4.x; acc[3][1] += a3 * b4.y; acc[3][2] += a3 * b4.z; acc[3][3] += a3 * b4.w;
        }
        __syncthreads();
    }

    float4 bb = make_float4(0.f, 0.f, 0.f, 0.f);
    if (bias) bb = *(const float4*)&bias[n0 + (tx << 2)];
#pragma unroll
    for (int i = 0; i < 4; i++) {
        int r = m0 + (ty << 2) + i;
        float4 o;
        o.x = acc[i][0] + bb.x; o.y = acc[i][1] + bb.y;
        o.z = acc[i][2] + bb.z; o.w = acc[i][3] + bb.w;
        if (ACT == 1) {
            o.x = fmaxf(o.x, 0.f); o.y = fmaxf(o.y, 0.f);
            o.z = fmaxf(o.z, 0.f); o.w = fmaxf(o.w, 0.f);
        }
        *(float4*)&C[(size_t)r * N + n0 + (tx << 2)] = o;
    }
}

// ---------------- fused recurrent step -------------------------------------
// gates = Z[t] + hprev @ Wrec ; then LSTM elementwise.
// Block computes a 64(batch) x 16(h) tile across all 4 gate groups.
__global__ __launch_bounds__(256) void lstm_step(const float* __restrict__ hprev,
                                                 const float* __restrict__ Wrec,  // [512,2048]
                                                 const float* __restrict__ Z,     // [B,2048] for this t
                                                 float* __restrict__ hout,        // [B,H]
                                                 float* __restrict__ cbuf) {      // [B,H]
    __shared__ float As[16][68];
    __shared__ float Bs[16][64];
    __shared__ float Gs[64][65];
    const int tid = threadIdx.x;
    const int m0 = blockIdx.y << 6;   // batch tile
    const int h0 = blockIdx.x << 4;   // h tile (16 wide)
    const int tx = tid & 15, ty = tid >> 4;
    const int ar = tid >> 2, ak = (tid & 3) << 2;
    const int bk = tid >> 4, bn = (tid & 15) << 2;
    const int bgate = bn >> 4, bh = bn & 15;

    float acc[4][4];
#pragma unroll
    for (int i = 0; i < 4; i++)
#pragma unroll
        for (int j = 0; j < 4; j++) acc[i][j] = 0.f;

    const float* Aptr = hprev + (size_t)(m0 + ar) * HH + ak;
    const float* Bptr = Wrec + (size_t)bk * NG + bgate * HH + h0 + bh;

    for (int k0 = 0; k0 < HH; k0 += 16) {
        float4 av = *(const float4*)(Aptr + k0);
        float4 bv = *(const float4*)(Bptr + (size_t)k0 * NG);
        As[ak + 0][ar] = av.x; As[ak + 1][ar] = av.y;
        As[ak + 2][ar] = av.z; As[ak + 3][ar] = av.w;
        *(float4*)&Bs[bk][bn] = bv;
        __syncthreads();
#pragma unroll
        for (int k = 0; k < 16; k++) {
            float4 b4 = *(const float4*)&Bs[k][tx << 2];
            float a0 = As[k][(ty << 2) + 0], a1 = As[k][(ty << 2) + 1];
            float a2 = As[k][(ty << 2) + 2], a3 = As[k][(ty << 2) + 3];
            acc[0][0] += a0 * b4.x; acc[0][1] += a0 * b4.y; acc[0][2] += a0 * b4.z; acc[0][3] += a0 * b4.w;
            acc[1][0] += a1 * b4.x; acc[1][1] += a1 * b4.y; acc[1][2] += a1 * b4.z; acc[1][3] += a1 * b4.w;
            acc[2][0] += a2 * b4.x; acc[2][1] += a2 * b4.y; acc[2][2] += a2 * b4.z; acc[2][3] += a2 * b4.w;
            acc[3][0] += a3 * b4.x; acc[3][1] += a3 * b4.y; acc[3][2] += a3 * b4.z; acc[3][3] += a3 * b4.w;
        }
        __syncthreads();
    }

    // epilogue: gates tile (local col c -> gate c>>4, h-offset c&15)
    const int cgate = tx >> 2;
    const int choff = (tx & 3) << 2;
#pragma unroll
    for (int i = 0; i < 4; i++) {
        int r = m0 + (ty << 2) + i;
        float4 zv = *(const float4*)&Z[(size_t)r * NG + cgate * HH + h0 + choff];
        Gs[(ty << 2) + i][(cgate << 4) + choff + 0] = acc[i][0] + zv.x;
        Gs[(ty << 2) + i][(cgate << 4) + choff + 1] = acc[i][1] + zv.y;
        Gs[(ty << 2) + i][(cgate << 4) + choff + 2] = acc[i][2] + zv.z;
        Gs[(ty << 2) + i][(cgate << 4) + choff + 3] = acc[i][3] + zv.w;
    }
    __syncthreads();

    const float mk0 = g_mask[0], mk1 = g_mask[1], mk2 = g_mask[2], mk3 = g_mask[3];
#pragma unroll
    for (int s = 0; s < 4; s++) {
        int e = tid + (s << 8);
        int r = e >> 4, hh = e & 15;
        float f  = Gs[r][hh];
        float ii = Gs[r][16 + hh];
        float gg = Gs[r][32 + hh];
        float oo = Gs[r][48 + hh];
        f  = mk0 / (1.f + expf(-f));
        ii = mk1 / (1.f + expf(-ii));
        gg = mk2 * tanhf(gg);
        oo = mk3 / (1.f + expf(-oo));
        size_t idx = (size_t)(m0 + r) * HH + h0 + hh;
        float c = f * cbuf[idx] + ii * gg;
        cbuf[idx] = c;
        hout[idx] = oo * tanhf(c);
    }
}

// ---------------- launch ----------------------------------------------------
extern "C" void kernel_launch(void* const* d_in, const int* in_sizes, int n_in,
                              void* d_out, int out_size) {
    (void)in_sizes; (void)n_in; (void)out_size;
    const float* inputs  = (const float*)d_in[0];
    const float* enc_w1  = (const float*)d_in[1];
    const float* enc_b1  = (const float*)d_in[2];
    const float* enc_w2  = (const float*)d_in[3];
    const float* enc_b2  = (const float*)d_in[4];
    const float* enc_w3  = (const float*)d_in[5];
    const float* enc_b3  = (const float*)d_in[6];
    const float* gate_w  = (const float*)d_in[7];
    const float* gate_b  = (const float*)d_in[8];
    const float* samp_w1 = (const float*)d_in[9];
    const float* samp_b1 = (const float*)d_in[10];
    const float* samp_w2 = (const float*)d_in[11];
    const float* samp_b2 = (const float*)d_in[12];

    float* out     = (float*)d_out;
    float* stacked = out;                                   // [T,B,H]
    float* hx      = out + (size_t)TT * BB * HH;            // [B,H]
    float* cx      = hx + (size_t)BB * HH;                  // [B,H]

    float *p_h1, *p_h2, *p_Z, *p_W3g, *p_bc, *p_zero;
    cudaGetSymbolAddress((void**)&p_h1,   g_h1);
    cudaGetSymbolAddress((void**)&p_h2,   g_h2);
    cudaGetSymbolAddress((void**)&p_Z,    g_Z);
    cudaGetSymbolAddress((void**)&p_W3g,  g_W3g);
    cudaGetSymbolAddress((void**)&p_bc,   g_bc);
    cudaGetSymbolAddress((void**)&p_zero, g_zero);

    const int M = TT * BB;  // 65536

    // state init + timestep-invariant precompute
    zero_kernel<<<(BB * HH + 255) / 256, 256>>>(cx, BB * HH);
    mask_kernel<<<1, 32>>>(samp_w1, samp_b1, samp_w2, samp_b2);
    bias_kernel<<<(NG + 255) / 256, 256>>>(gate_w, gate_b, enc_b3);
    // W3g = enc_w3 @ gate_w_top  (collapses the K=512 GEMM into K=64)
    sgemm<0><<<dim3(NG / 64, 1), 256>>>(enc_w3, gate_w, nullptr, p_W3g, 64, NG, DD);
    // encoder (parallel over all T*B rows)
    sgemm<1><<<dim3(128 / 64, M / 64), 256>>>(inputs, enc_w1, enc_b1, p_h1, M, 128, DD);
    sgemm<1><<<dim3(64 / 64, M / 64), 256>>>(p_h1, enc_w2, enc_b2, p_h2, M, 64, 128);
    // Z = H2 @ W3g + (b3@Wg_top + gate_b)
    sgemm<0><<<dim3(NG / 64, M / 64), 256>>>(p_h2, p_W3g, p_bc, p_Z, M, NG, 64);

    // sequential scan; hx chained through the output buffer itself
    const float* Wrec = gate_w + (size_t)DD * NG;
    for (int t = 0; t < TT; t++) {
        const float* hp = (t == 0) ? p_zero : stacked + (size_t)(t - 1) * BB * HH;
        lstm_step<<<dim3(HH / 16, BB / 64), 256>>>(
            hp, Wrec, p_Z + (size_t)t * BB * NG,
            stacked + (size_t)t * BB * HH, cx);
    }

    cudaMemcpyAsync(hx, stacked + (size_t)(TT - 1) * BB * HH,
                    (size_t)BB * HH * sizeof(float), cudaMemcpyDeviceToDevice);
}

// round 4
// speedup vs baseline: 1.0009x; 1.0009x over previous
#include <cuda_runtime.h>
#include <math.h>

#define TT 256
#define BB 256
#define DD 512
#define HH 512
#define NG 2048  // 4*H

// ---------------- scratch (static device globals; no allocations) ----------
__device__ float g_mask[4];
__device__ float g_bc[NG];                       // b3 @ Wg_top + gate_b
__device__ float g_W3g[64 * NG];                 // W3 @ Wg_top
__device__ float g_h1[(size_t)TT * BB * 128];
__device__ float g_h2[(size_t)TT * BB * 64];
__device__ float g_Z[(size_t)TT * BB * NG];      // precomputed input-gate contributions
__device__ float g_zero[BB * HH];                // never written -> stays zero

// ---------------- tiny kernels --------------------------------------------
__global__ void mask_kernel(const float* __restrict__ w1, const float* __restrict__ b1,
                            const float* __restrict__ w2, const float* __restrict__ b2) {
    if (threadIdx.x == 0) {
        float t[8];
        for (int j = 0; j < 8; j++) {
            float s = b1[j];
            for (int i = 0; i < 4; i++) s += w1[i * 8 + j];
            t[j] = tanhf(s);
        }
        float z[4];
        float mx = -1e30f;
        for (int k = 0; k < 4; k++) {
            float s = b2[k];
            for (int j = 0; j < 8; j++) s += t[j] * w2[j * 4 + k];
            z[k] = s;
            mx = fmaxf(mx, s);
        }
        float den = 0.f;
        for (int k = 0; k < 4; k++) { z[k] = expf(z[k] - mx); den += z[k]; }
        for (int k = 0; k < 4; k++) g_mask[k] = z[k] / den;
    }
}

__global__ void bias_kernel(const float* __restrict__ gate_w, const float* __restrict__ gate_b,
                            const float* __restrict__ b3) {
    int n = blockIdx.x * blockDim.x + threadIdx.x;
    if (n < NG) {
        float s = gate_b[n];
        for (int k = 0; k < DD; k++) s += b3[k] * gate_w[(size_t)k * NG + n];
        g_bc[n] = s;
    }
}

__global__ void zero_kernel(float* __restrict__ p, int n) {
    int i = blockIdx.x * blockDim.x + threadIdx.x;
    if (i < n) p[i] = 0.f;
}

// ---------------- generic fp32 GEMM: C = act(A@B + bias) -------------------
// A [M,K] row-major, B [K,N] row-major. M%64==0 (or M==64), N%64==0, K%16==0.
template <int ACT>
__global__ __launch_bounds__(256) void sgemm(const float* __restrict__ A,
                                             const float* __restrict__ B,
                                             const float* __restrict__ bias,
                                             float* __restrict__ C,
                                             int M, int N, int K) {
    __shared__ float As[16][68];
    __shared__ float Bs[16][64];
    const int tid = threadIdx.x;
    const int m0 = blockIdx.y << 6, n0 = blockIdx.x << 6;
    const int tx = tid & 15, ty = tid >> 4;
    const int ar = tid >> 2, ak = (tid & 3) << 2;
    const int bk = tid >> 4, bn = (tid & 15) << 2;

    float acc[4][4];
#pragma unroll
    for (int i = 0; i < 4; i++)
#pragma unroll
        for (int j = 0; j < 4; j++) acc[i][j] = 0.f;

    const float* Aptr = A + (size_t)(m0 + ar) * K + ak;
    const float* Bptr = B + (size_t)bk * N + n0 + bn;

    for (int k0 = 0; k0 < K; k0 += 16) {
        float4 av = *(const float4*)(Aptr + k0);
        float4 bv = *(const float4*)(Bptr + (size_t)k0 * N);
        As[ak + 0][ar] = av.x; As[ak + 1][ar] = av.y;
        As[ak + 2][ar] = av.z; As[ak + 3][ar] = av.w;
        *(float4*)&Bs[bk][bn] = bv;
        __syncthreads();
#pragma unroll
        for (int k = 0; k < 16; k++) {
            float4 b4 = *(const float4*)&Bs[k][tx << 2];
            float a0 = As[k][(ty << 2) + 0], a1 = As[k][(ty << 2) + 1];
            float a2 = As[k][(ty << 2) + 2], a3 = As[k][(ty << 2) + 3];
            acc[0][0] += a0 * b4.x; acc[0][1] += a0 * b4.y; acc[0][2] += a0 * b4.z; acc[0][3] += a0 * b4.w;
            acc[1][0] += a1 * b4.x; acc[1][1] += a1 * b4.y; acc[1][2] += a1 * b4.z; acc[1][3] += a1 * b4.w;
            acc[2][0] += a2 * b4.x; acc[2][1] += a2 * b4.y; acc[2][2] += a2 * b4.z; acc[2][3] += a2 * b4.w;
            acc[3][0] += a3 * b4.x; acc[3][1] += a3 * b4.y; acc[3][2] += a3 * b4.z; acc[3][3] += a3 * b4.w;
        }
        __syncthreads();
    }

    float4 bb = make_float4(0.f, 0.f, 0.f, 0.f);
    if (bias) bb = *(const float4*)&bias[n0 + (tx << 2)];
#pragma unroll
    for (int i = 0; i < 4; i++) {
        int r = m0 + (ty << 2) + i;
        float4 o;
        o.x = acc[i][0] + bb.x; o.y = acc[i][1] + bb.y;
        o.z = acc[i][2] + bb.z; o.w = acc[i][3] + bb.w;
        if (ACT == 1) {
            o.x = fmaxf(o.x, 0.f); o.y = fmaxf(o.y, 0.f);
            o.z = fmaxf(o.z, 0.f); o.w = fmaxf(o.w, 0.f);
        }
        *(float4*)&C[(size_t)r * N + n0 + (tx << 2)] = o;
    }
}

// ---------------- fused recurrent step -------------------------------------
// gates = Z[t] + hprev @ Wrec ; then LSTM elementwise.
// Block computes a 64(batch) x 16(h) tile across all 4 gate groups.
__global__ __launch_bounds__(256) void lstm_step(const float* __restrict__ hprev,
                                                 const float* __restrict__ Wrec,  // [512,2048]
                                                 const float* __restrict__ Z,     // [B,2048] for this t
                                                 float* __restrict__ hout,        // [B,H]
                                                 float* __restrict__ cbuf) {      // [B,H]
    __shared__ float As[16][68];
    __shared__ float Bs[16][64];
    __shared__ float Gs[64][65];
    const int tid = threadIdx.x;
    const int m0 = blockIdx.y << 6;   // batch tile
    const int h0 = blockIdx.x << 4;   // h tile (16 wide)
    const int tx = tid & 15, ty = tid >> 4;
    const int ar = tid >> 2, ak = (tid & 3) << 2;
    const int bk = tid >> 4, bn = (tid & 15) << 2;
    const int bgate = bn >> 4, bh = bn & 15;

    float acc[4][4];
#pragma unroll
    for (int i = 0; i < 4; i++)
#pragma unroll
        for (int j = 0; j < 4; j++) acc[i][j] = 0.f;

    const float* Aptr = hprev + (size_t)(m0 + ar) * HH + ak;
    const float* Bptr = Wrec + (size_t)bk * NG + bgate * HH + h0 + bh;

    for (int k0 = 0; k0 < HH; k0 += 16) {
        float4 av = *(const float4*)(Aptr + k0);
        float4 bv = *(const float4*)(Bptr + (size_t)k0 * NG);
        As[ak + 0][ar] = av.x; As[ak + 1][ar] = av.y;
        As[ak + 2][ar] = av.z; As[ak + 3][ar] = av.w;
        *(float4*)&Bs[bk][bn] = bv;
        __syncthreads();
#pragma unroll
        for (int k = 0; k < 16; k++) {
            float4 b4 = *(const float4*)&Bs[k][tx << 2];
            float a0 = As[k][(ty << 2) + 0], a1 = As[k][(ty << 2) + 1];
            float a2 = As[k][(ty << 2) + 2], a3 = As[k][(ty << 2) + 3];
            acc[0][0] += a0 * b4.x; acc[0][1] += a0 * b4.y; acc[0][2] += a0 * b4.z; acc[0][3] += a0 * b4.w;
            acc[1][0] += a1 * b4.x; acc[1][1] += a1 * b4.y; acc[1][2] += a1 * b4.z; acc[1][3] += a1 * b4.w;
            acc[2][0] += a2 * b4.x; acc[2][1] += a2 * b4.y; acc[2][2] += a2 * b4.z; acc[2][3] += a2 * b4.w;
            acc[3][0] += a3 * b4.x; acc[3][1] += a3 * b4.y; acc[3][2] += a3 * b4.z; acc[3][3] += a3 * b4.w;
        }
        __syncthreads();
    }

    // epilogue: gates tile (local col c -> gate c>>4, h-offset c&15)
    const int cgate = tx >> 2;
    const int choff = (tx & 3) << 2;
#pragma unroll
    for (int i = 0; i < 4; i++) {
        int r = m0 + (ty << 2) + i;
        float4 zv = *(const float4*)&Z[(size_t)r * NG + cgate * HH + h0 + choff];
        Gs[(ty << 2) + i][(cgate << 4) + choff + 0] = acc[i][0] + zv.x;
        Gs[(ty << 2) + i][(cgate << 4) + choff + 1] = acc[i][1] + zv.y;
        Gs[(ty << 2) + i][(cgate << 4) + choff + 2] = acc[i][2] + zv.z;
        Gs[(ty << 2) + i][(cgate << 4) + choff + 3] = acc[i][3] + zv.w;
    }
    __syncthreads();

    const float mk0 = g_mask[0], mk1 = g_mask[1], mk2 = g_mask[2], mk3 = g_mask[3];
#pragma unroll
    for (int s = 0; s < 4; s++) {
        int e = tid + (s << 8);
        int r = e >> 4, hh = e & 15;
        float f  = Gs[r][hh];
        float ii = Gs[r][16 + hh];
        float gg = Gs[r][32 + hh];
        float oo = Gs[r][48 + hh];
        f  = mk0 / (1.f + expf(-f));
        ii = mk1 / (1.f + expf(-ii));
        gg = mk2 * tanhf(gg);
        oo = mk3 / (1.f + expf(-oo));
        size_t idx = (size_t)(m0 + r) * HH + h0 + hh;
        float c = f * cbuf[idx] + ii * gg;
        cbuf[idx] = c;
        hout[idx] = oo * tanhf(c);
    }
}

// ---------------- launch ----------------------------------------------------
extern "C" void kernel_launch(void* const* d_in, const int* in_sizes, int n_in,
                              void* d_out, int out_size) {
    (void)in_sizes; (void)n_in; (void)out_size;
    const float* inputs  = (const float*)d_in[0];
    const float* enc_w1  = (const float*)d_in[1];
    const float* enc_b1  = (const float*)d_in[2];
    const float* enc_w2  = (const float*)d_in[3];
    const float* enc_b2  = (const float*)d_in[4];
    const float* enc_w3  = (const float*)d_in[5];
    const float* enc_b3  = (const float*)d_in[6];
    const float* gate_w  = (const float*)d_in[7];
    const float* gate_b  = (const float*)d_in[8];
    const float* samp_w1 = (const float*)d_in[9];
    const float* samp_b1 = (const float*)d_in[10];
    const float* samp_w2 = (const float*)d_in[11];
    const float* samp_b2 = (const float*)d_in[12];

    float* out     = (float*)d_out;
    float* stacked = out;                                   // [T,B,H]
    float* hx      = out + (size_t)TT * BB * HH;            // [B,H]
    float* cx      = hx + (size_t)BB * HH;                  // [B,H]

    float *p_h1, *p_h2, *p_Z, *p_W3g, *p_bc, *p_zero;
    cudaGetSymbolAddress((void**)&p_h1,   g_h1);
    cudaGetSymbolAddress((void**)&p_h2,   g_h2);
    cudaGetSymbolAddress((void**)&p_Z,    g_Z);
    cudaGetSymbolAddress((void**)&p_W3g,  g_W3g);
    cudaGetSymbolAddress((void**)&p_bc,   g_bc);
    cudaGetSymbolAddress((void**)&p_zero, g_zero);

    const int M = TT * BB;  // 65536

    // state init + timestep-invariant precompute
    zero_kernel<<<(BB * HH + 255) / 256, 256>>>(cx, BB * HH);
    mask_kernel<<<1, 32>>>(samp_w1, samp_b1, samp_w2, samp_b2);
    bias_kernel<<<(NG + 255) / 256, 256>>>(gate_w, gate_b, enc_b3);
    // W3g = enc_w3 @ gate_w_top  (collapses the K=512 GEMM into K=64)
    sgemm<0><<<dim3(NG / 64, 1), 256>>>(enc_w3, gate_w, nullptr, p_W3g, 64, NG, DD);
    // encoder (parallel over all T*B rows)
    sgemm<1><<<dim3(128 / 64, M / 64), 256>>>(inputs, enc_w1, enc_b1, p_h1, M, 128, DD);
    sgemm<1><<<dim3(64 / 64, M / 64), 256>>>(p_h1, enc_w2, enc_b2, p_h2, M, 64, 128);
    // Z = H2 @ W3g + (b3@Wg_top + gate_b)
    sgemm<0><<<dim3(NG / 64, M / 64), 256>>>(p_h2, p_W3g, p_bc, p_Z, M, NG, 64);

    // sequential scan; hx chained through the output buffer itself
    const float* Wrec = gate_w + (size_t)DD * NG;
    for (int t = 0; t < TT; t++) {
        const float* hp = (t == 0) ? p_zero : stacked + (size_t)(t - 1) * BB * HH;
        lstm_step<<<dim3(HH / 16, BB / 64), 256>>>(
            hp, Wrec, p_Z + (size_t)t * BB * NG,
            stacked + (size_t)t * BB * HH, cx);
    }

    cudaMemcpyAsync(hx, stacked + (size_t)(TT - 1) * BB * HH,
                    (size_t)BB * HH * sizeof(float), cudaMemcpyDeviceToDevice);
}

// round 11
// speedup vs baseline: 2.7344x; 2.7320x over previous
#include <cuda_runtime.h>
#include <cuda_fp16.h>
#include <math.h>
#include <stdint.h>

#define TT 256
#define BB 256
#define DD 512
#define HH 512
#define NG 2048

// ---------------- device globals ---------------------------------------------
__device__ float g_mask[4];
__device__ float g_bc[NG];
__device__ float g_bcp[NG];
__device__ float g_W3g[64 * NG];
__device__ float g_h1[(size_t)TT * BB * 128];
__device__ float g_h2[(size_t)TT * BB * 64];
__device__ __half g_h2h[(size_t)TT * BB * 64];
__device__ __half g_h2l[(size_t)TT * BB * 64];
__device__ uint4 g_Wp[294912];                    // packed B fragments (hi/lo)
__device__ __half g_hh[2][(size_t)BB * HH];       // h ping-pong hi
__device__ __half g_hl[2][(size_t)BB * HH];       // h ping-pong lo
__device__ __half g_zh[(size_t)BB * HH];          // stays zero

// ---------------- tiny kernels ----------------------------------------------
__global__ void mask_kernel(const float* __restrict__ w1, const float* __restrict__ b1,
                            const float* __restrict__ w2, const float* __restrict__ b2) {
    if (threadIdx.x == 0) {
        float t[8];
        for (int j = 0; j < 8; j++) {
            float s = b1[j];
            for (int i = 0; i < 4; i++) s += w1[i * 8 + j];
            t[j] = tanhf(s);
        }
        float z[4]; float mx = -1e30f;
        for (int k = 0; k < 4; k++) {
            float s = b2[k];
            for (int j = 0; j < 8; j++) s += t[j] * w2[j * 4 + k];
            z[k] = s; mx = fmaxf(mx, s);
        }
        float den = 0.f;
        for (int k = 0; k < 4; k++) { z[k] = expf(z[k] - mx); den += z[k]; }
        for (int k = 0; k < 4; k++) g_mask[k] = z[k] / den;
    }
}

__global__ void bias_kernel(const float* __restrict__ gate_w, const float* __restrict__ gate_b,
                            const float* __restrict__ b3) {
    int n = blockIdx.x * blockDim.x + threadIdx.x;
    if (n < NG) {
        float s = gate_b[n];
        for (int k = 0; k < DD; k++) s += b3[k] * gate_w[(size_t)k * NG + n];
        g_bc[n] = s;
    }
}

__global__ void bcpack_kernel() {
    int idx = blockIdx.x * blockDim.x + threadIdx.x;
    if (idx < NG) {
        int G = idx >> 6, c = idx & 63;
        g_bcp[idx] = g_bc[(c >> 4) * 512 + G * 16 + (c & 15)];
    }
}

__global__ void zero_kernel(float* __restrict__ p, int n) {
    int i = blockIdx.x * blockDim.x + threadIdx.x;
    if (i < n) p[i] = 0.f;
}

__global__ void h2split_kernel() {
    size_t idx = (size_t)blockIdx.x * blockDim.x + threadIdx.x;
    if (idx < (size_t)TT * BB * 64) {
        float v = g_h2[idx];
        __half hi = __float2half(v);
        g_h2h[idx] = hi;
        g_h2l[idx] = __float2half(v - __half2float(hi));
    }
}

__device__ __forceinline__ uint32_t packh(__half a, __half b) {
    return (uint32_t)__half_as_ushort(a) | ((uint32_t)__half_as_ushort(b) << 16);
}

// Pack W = [Wrec ; W3g] (gate-col permuted) into mma B-fragment order.
// Linear uint4 index: ((cw*36 + ks)*2 + j)*32 + lane, cw = cg*4 + w.
__global__ void pack_W_kernel(const float* __restrict__ gate_w) {
    const float* Wrec = gate_w + (size_t)DD * NG;
    int idx = blockIdx.x * blockDim.x + threadIdx.x;
    if (idx >= 294912) return;
    int l = idx & 31;
    int j = (idx >> 5) & 1;
    int ks = (idx >> 6) % 36;
    int cw = idx / 2304;
    int w = cw & 3, cg = cw >> 2;
    int c = w * 16 + j * 8 + (l >> 2);               // local col [0,64)
    int col = (c >> 4) * 512 + cg * 16 + (c & 15);   // global gate col
    int k0 = ks * 16 + (l & 3) * 2;
    float v[4];
#pragma unroll
    for (int e = 0; e < 4; e++) {
        int k = k0 + (e >> 1) * 8 + (e & 1);
        v[e] = (k < 512) ? Wrec[(size_t)k * NG + col] : g_W3g[(size_t)(k - 512) * NG + col];
    }
    __half hi[4], lo[4];
#pragma unroll
    for (int e = 0; e < 4; e++) {
        hi[e] = __float2half(v[e]);
        lo[e] = __float2half(v[e] - __half2float(hi[e]));
    }
    uint4 o;
    o.x = packh(hi[0], hi[1]); o.y = packh(hi[2], hi[3]);
    o.z = packh(lo[0], lo[1]); o.w = packh(lo[2], lo[3]);
    g_Wp[idx] = o;
}

// ---------------- fp32 SGEMM (encoder / W3g) --------------------------------
template <int ACT>
__global__ __launch_bounds__(256) void sgemm(const float* __restrict__ A,
                                             const float* __restrict__ B,
                                             const float* __restrict__ bias,
                                             float* __restrict__ C,
                                             int M, int N, int K) {
    __shared__ float As[16][68];
    __shared__ float Bs[16][64];
    const int tid = threadIdx.x;
    const int m0 = blockIdx.y << 6, n0 = blockIdx.x << 6;
    const int tx = tid & 15, ty = tid >> 4;
    const int ar = tid >> 2, ak = (tid & 3) << 2;
    const int bk = tid >> 4, bn = (tid & 15) << 2;
    float acc[4][4];
#pragma unroll
    for (int i = 0; i < 4; i++)
#pragma unroll
        for (int jj = 0; jj < 4; jj++) acc[i][jj] = 0.f;
    const float* Aptr = A + (size_t)(m0 + ar) * K + ak;
    const float* Bptr = B + (size_t)bk * N + n0 + bn;
    for (int k0 = 0; k0 < K; k0 += 16) {
        float4 av = *(const float4*)(Aptr + k0);
        float4 bv = *(const float4*)(Bptr + (size_t)k0 * N);
        As[ak + 0][ar] = av.x; As[ak + 1][ar] = av.y;
        As[ak + 2][ar] = av.z; As[ak + 3][ar] = av.w;
        *(float4*)&Bs[bk][bn] = bv;
        __syncthreads();
#pragma unroll
        for (int k = 0; k < 16; k++) {
            float4 b4 = *(const float4*)&Bs[k][tx << 2];
            float a0 = As[k][(ty << 2) + 0], a1 = As[k][(ty << 2) + 1];
            float a2 = As[k][(ty << 2) + 2], a3 = As[k][(ty << 2) + 3];
            acc[0][0] += a0 * b4.x; acc[0][1] += a0 * b4.y; acc[0][2] += a0 * b4.z; acc[0][3] += a0 * b4.w;
            acc[1][0] += a1 * b4.x; acc[1][1] += a1 * b4.y; acc[1][2] += a1 * b4.z; acc[1][3] += a1 * b4.w;
            acc[2][0] += a2 * b4.x; acc[2][1] += a2 * b4.y; acc[2][2] += a2 * b4.z; acc[2][3] += a2 * b4.w;
            acc[3][0] += a3 * b4.x; acc[3][1] += a3 * b4.y; acc[3][2] += a3 * b4.z; acc[3][3] += a3 * b4.w;
        }
        __syncthreads();
    }
    float4 bb = make_float4(0.f, 0.f, 0.f, 0.f);
    if (bias) bb = *(const float4*)&bias[n0 + (tx << 2)];
#pragma unroll
    for (int i = 0; i < 4; i++) {
        int r = m0 + (ty << 2) + i;
        float4 o;
        o.x = acc[i][0] + bb.x; o.y = acc[i][1] + bb.y;
        o.z = acc[i][2] + bb.z; o.w = acc[i][3] + bb.w;
        if (ACT == 1) {
            o.x = fmaxf(o.x, 0.f); o.y = fmaxf(o.y, 0.f);
            o.z = fmaxf(o.z, 0.f); o.w = fmaxf(o.w, 0.f);
        }
        *(float4*)&C[(size_t)r * N + n0 + (tx << 2)] = o;
    }
}

// ---------------- helpers ----------------------------------------------------
__device__ __forceinline__ uint32_t smem_u32(const void* p) {
    uint32_t a;
    asm("{ .reg .u64 t; cvta.to.shared.u64 t, %1; cvt.u32.u64 %0, t; }" : "=r"(a) : "l"(p));
    return a;
}
__device__ __forceinline__ void cpa16(uint32_t d, const void* s) {
    asm volatile("cp.async.cg.shared.global [%0], [%1], 16;" :: "r"(d), "l"(s));
}
__device__ __forceinline__ void ldsm4(uint32_t* r, uint32_t a) {
    asm volatile("ldmatrix.sync.aligned.m8n8.x4.shared.b16 {%0,%1,%2,%3}, [%4];"
                 : "=r"(r[0]), "=r"(r[1]), "=r"(r[2]), "=r"(r[3]) : "r"(a));
}
__device__ __forceinline__ void mma16816(float* c, const uint32_t* a, uint32_t b0, uint32_t b1) {
    asm volatile("mma.sync.aligned.m16n8k16.row.col.f32.f16.f16.f32 "
                 "{%0,%1,%2,%3}, {%4,%5,%6,%7}, {%8,%9}, {%0,%1,%2,%3};"
                 : "+f"(c[0]), "+f"(c[1]), "+f"(c[2]), "+f"(c[3])
                 : "r"(a[0]), "r"(a[1]), "r"(a[2]), "r"(a[3]), "r"(b0), "r"(b1));
}

// ---------------- fused recurrent step (mma.sync) ---------------------------
// CTA: 64 batch rows (blockIdx.y) x col-group cg (blockIdx.x): 64 gate cols =
// {q*512 + cg*16 + j}. Warp w handles gate q=w. K = 576 = 9 chunks of 64.
// Gs (gates staging) ALIASES the A double-buffer: only used after the mainloop.
#define SM_A     256
#define SM_GS    SM_A
#define SM_BYTES (256 + 2 * 16384)  // 33024 < 48KB default

__global__ __launch_bounds__(128, 1) void step_kernel(
    const __half* __restrict__ ph, const __half* __restrict__ pl,
    const __half* __restrict__ h2h, const __half* __restrict__ h2l,
    __half* __restrict__ nh, __half* __restrict__ nl,
    float* __restrict__ hout, float* __restrict__ cbuf) {
    extern __shared__ char smem[];
    const uint32_t sb = smem_u32(smem);
    const int tid = threadIdx.x, lane = tid & 31, w = tid >> 5;
    const int cg = blockIdx.x, m0 = blockIdx.y << 6;
    const float bias_reg = g_bcp[cg * 64 + (tid & 63)];

    auto loadA = [&](int b, const __half* sh, const __half* sl, int stride, int c0) {
        uint32_t base = sb + SM_A + b * 16384;
#pragma unroll
        for (int i = 0; i < 4; i++) {
            int c = tid + (i << 7);
            int r = c >> 3, c16 = c & 7;
            uint32_t off = (uint32_t)(r * 128 + ((c16 ^ (r & 7)) << 4));
            cpa16(base + off,        sh + (size_t)r * stride + c0 + c16 * 8);
            cpa16(base + 8192 + off, sl + (size_t)r * stride + c0 + c16 * 8);
        }
        asm volatile("cp.async.commit_group;" ::: "memory");
    };

    float C[4][2][4];
#pragma unroll
    for (int mi = 0; mi < 4; mi++)
#pragma unroll
        for (int j = 0; j < 2; j++)
#pragma unroll
            for (int e = 0; e < 4; e++) C[mi][j][e] = 0.f;

    const __half* phr = ph + (size_t)m0 * HH;
    const __half* plr = pl + (size_t)m0 * HH;
    loadA(0, phr, plr, HH, 0);
    loadA(1, phr, plr, HH, 64);

    const int arow = lane & 15, ahalf = lane >> 4;
    const uint4* Wp = g_Wp + (size_t)(cg * 4 + w) * 2304 + lane;

    for (int ch = 0; ch < 9; ch++) {
        const int b = ch & 1;
        if (ch < 8) asm volatile("cp.async.wait_group 1;" ::: "memory");
        else        asm volatile("cp.async.wait_group 0;" ::: "memory");
        __syncthreads();
        uint32_t abase = sb + SM_A + b * 16384;
#pragma unroll
        for (int kc = 0; kc < 4; kc++) {
            int ks = ch * 4 + kc;
            uint4 B0 = Wp[ks * 64];
            uint4 B1 = Wp[ks * 64 + 32];
            uint32_t a0 = abase + (uint32_t)(arow * 128 +
                          ((((kc << 1) + ahalf) ^ (arow & 7)) << 4));
#pragma unroll
            for (int mi = 0; mi < 4; mi++) {
                uint32_t Ah[4], Al[4];
                ldsm4(Ah, a0 + mi * 2048);
                ldsm4(Al, a0 + mi * 2048 + 8192);
                mma16816(C[mi][0], Ah, B0.x, B0.y);
                mma16816(C[mi][0], Al, B0.x, B0.y);
                mma16816(C[mi][0], Ah, B0.z, B0.w);
                mma16816(C[mi][1], Ah, B1.x, B1.y);
                mma16816(C[mi][1], Al, B1.x, B1.y);
                mma16816(C[mi][1], Ah, B1.z, B1.w);
            }
        }
        __syncthreads();
        if (ch + 2 <= 8) {
            if (ch + 2 < 8) loadA(b, phr, plr, HH, (ch + 2) * 64);
            else loadA(b, h2h + (size_t)m0 * 64, h2l + (size_t)m0 * 64, 64, 0);
        }
    }
    // drain pending cp.async groups, then reuse the A region as gates staging
    asm volatile("cp.async.wait_group 0;" ::: "memory");
    __syncthreads();

    float* Gs = (float*)(smem + SM_GS);
    float* bs = Gs + 64 * 68;
#pragma unroll
    for (int mi = 0; mi < 4; mi++)
#pragma unroll
        for (int j = 0; j < 2; j++) {
            int row = mi * 16 + (lane >> 2);
            int col = w * 16 + j * 8 + ((lane & 3) << 1);
            Gs[row * 68 + col]           = C[mi][j][0];
            Gs[row * 68 + col + 1]       = C[mi][j][1];
            Gs[(row + 8) * 68 + col]     = C[mi][j][2];
            Gs[(row + 8) * 68 + col + 1] = C[mi][j][3];
        }
    if (tid < 64) bs[tid] = bias_reg;
    __syncthreads();
    const float mk0 = g_mask[0], mk1 = g_mask[1], mk2 = g_mask[2], mk3 = g_mask[3];
#pragma unroll
    for (int i = 0; i < 8; i++) {
        int e = tid + (i << 7);
        int row = e >> 4, jj = e & 15;
        float F = Gs[row * 68 + jj]      + bs[jj];
        float I = Gs[row * 68 + 16 + jj] + bs[16 + jj];
        float G = Gs[row * 68 + 32 + jj] + bs[32 + jj];
        float O = Gs[row * 68 + 48 + jj] + bs[48 + jj];
        float f  = mk0 / (1.f + expf(-F));
        float ii = mk1 / (1.f + expf(-I));
        float gg = mk2 * tanhf(G);
        float oo = mk3 / (1.f + expf(-O));
        size_t idx = (size_t)(m0 + row) * HH + cg * 16 + jj;
        float c = f * cbuf[idx] + ii * gg;
        cbuf[idx] = c;
        float h = oo * tanhf(c);
        hout[idx] = h;
        __half hh = __float2half(h);
        nh[idx] = hh;
        nl[idx] = __float2half(h - __half2float(hh));
    }
}

// ---------------- launch -----------------------------------------------------
extern "C" void kernel_launch(void* const* d_in, const int* in_sizes, int n_in,
                              void* d_out, int out_size) {
    (void)in_sizes; (void)n_in; (void)out_size;
    const float* inputs  = (const float*)d_in[0];
    const float* enc_w1  = (const float*)d_in[1];
    const float* enc_b1  = (const float*)d_in[2];
    const float* enc_w2  = (const float*)d_in[3];
    const float* enc_b2  = (const float*)d_in[4];
    const float* enc_w3  = (const float*)d_in[5];
    const float* enc_b3  = (const float*)d_in[6];
    const float* gate_w  = (const float*)d_in[7];
    const float* gate_b  = (const float*)d_in[8];
    const float* samp_w1 = (const float*)d_in[9];
    const float* samp_b1 = (const float*)d_in[10];
    const float* samp_w2 = (const float*)d_in[11];
    const float* samp_b2 = (const float*)d_in[12];

    float* out     = (float*)d_out;
    float* stacked = out;
    float* hx      = out + (size_t)TT * BB * HH;
    float* cx      = hx + (size_t)BB * HH;

    float *p_h1, *p_h2, *p_W3g;
    __half *p_h2h, *p_h2l, *p_hh, *p_hl, *p_zh;
    cudaGetSymbolAddress((void**)&p_h1,  g_h1);
    cudaGetSymbolAddress((void**)&p_h2,  g_h2);
    cudaGetSymbolAddress((void**)&p_W3g, g_W3g);
    cudaGetSymbolAddress((void**)&p_h2h, g_h2h);
    cudaGetSymbolAddress((void**)&p_h2l, g_h2l);
    cudaGetSymbolAddress((void**)&p_hh,  g_hh);
    cudaGetSymbolAddress((void**)&p_hl,  g_hl);
    cudaGetSymbolAddress((void**)&p_zh,  g_zh);

    const int M = TT * BB;

    zero_kernel<<<(BB * HH + 255) / 256, 256>>>(cx, BB * HH);
    mask_kernel<<<1, 32>>>(samp_w1, samp_b1, samp_w2, samp_b2);
    bias_kernel<<<(NG + 255) / 256, 256>>>(gate_w, gate_b, enc_b3);
    sgemm<0><<<dim3(NG / 64, 1), 256>>>(enc_w3, gate_w, nullptr, p_W3g, 64, NG, DD);
    bcpack_kernel<<<NG / 256, 256>>>();
    pack_W_kernel<<<(294912 + 255) / 256, 256>>>(gate_w);
    sgemm<1><<<dim3(2, M / 64), 256>>>(inputs, enc_w1, enc_b1, p_h1, M, 128, DD);
    sgemm<1><<<dim3(1, M / 64), 256>>>(p_h1, enc_w2, enc_b2, p_h2, M, 64, 128);
    h2split_kernel<<<(int)(((size_t)TT * BB * 64) / 256), 256>>>();

    for (int t = 0; t < TT; t++) {
        const __half* rh = (t == 0) ? p_zh : p_hh + (size_t)((t - 1) & 1) * BB * HH;
        const __half* rl = (t == 0) ? p_zh : p_hl + (size_t)((t - 1) & 1) * BB * HH;
        step_kernel<<<dim3(32, 4), 128, SM_BYTES>>>(
            rh, rl,
            p_h2h + (size_t)t * BB * 64, p_h2l + (size_t)t * BB * 64,
            p_hh + (size_t)(t & 1) * BB * HH, p_hl + (size_t)(t & 1) * BB * HH,
            stacked + (size_t)t * BB * HH, cx);
    }

    cudaMemcpyAsync(hx, stacked + (size_t)(TT - 1) * BB * HH,
                    (size_t)BB * HH * sizeof(float), cudaMemcpyDeviceToDevice);
}